// round 17
// baseline (speedup 1.0000x reference)
#include <cuda_runtime.h>

#define NMAX 100000
#define D 32
#define NBN ((NMAX + 255) / 256)   // 391 node-blocks

// ---- persistent scratch (device globals; zero-initialized at load) ----
__device__ float  d_q[NMAX];        // q[n] = dinv[n] * y[n]
__device__ float  d_y[NMAX];        // y[n] = u . p[n] + c2 (unnormalized)
__device__ float  d_sacc[NMAX];     // scalar accumulator, init = q (self loop)
__device__ float  d_dinv[NMAX];
__device__ int    d_deg[NMAX];      // starts 0; qmul_k re-zeroes after read
__device__ double d_part[NBN][5];   // per-block x-moment partials
__device__ float  d_C;              // wb . gcn_b + bb

// ---------------------------------------------------------------------------
// 1) stats_k: x moments only. Trigger@start so degY launches immediately.
__global__ void __launch_bounds__(256) stats_k(const float* __restrict__ x, int n) {
    cudaTriggerProgrammaticLaunchCompletion();
    __shared__ double sred[8][5];
    int t = threadIdx.x;
    int node = blockIdx.x * 256 + t;
    float a = 0.f, b = 0.f;
    if (node < n) {
        float2 xv = ((const float2*)x)[node];
        a = xv.x; b = xv.y;
    }
    float s[5] = { a, b, a * a, b * b, a * b };
#pragma unroll
    for (int o = 16; o; o >>= 1)
#pragma unroll
        for (int j = 0; j < 5; j++) s[j] += __shfl_xor_sync(0xffffffffu, s[j], o);
    if ((t & 31) == 0)
#pragma unroll
        for (int j = 0; j < 5; j++) sred[t >> 5][j] = (double)s[j];
    __syncthreads();
    if (t < 5) {
        double acc = 0.0;
#pragma unroll
        for (int w = 0; w < 8; w++) acc += sred[w][t];
        d_part[blockIdx.x][t] = acc;
    }
}

// 2) degY_k: ALL blocks do a deg-histogram slice (independent of stats).
//    Blocks < nbn additionally: weight prologue (inputs only), ONE mid-kernel
//    sync on stats_k, then BN-fold + y[n]. Deg and encode overlap inside one
//    grid via dynamic block scheduling — no grid barrier, no trailing sync.
__global__ void __launch_bounds__(256) degY_k(
    const int* __restrict__ dst, int nT8, int Etail,
    const float* __restrict__ x,
    const float* __restrict__ w1, const float* __restrict__ b1,
    const float* __restrict__ gam, const float* __restrict__ bet,
    const float* __restrict__ pa,
    const float* __restrict__ w2, const float* __restrict__ b2,
    const float* __restrict__ gw, const float* __restrict__ gb,
    const float* __restrict__ wb, const float* __restrict__ bb,
    int n, int nbn) {
    cudaTriggerProgrammaticLaunchCompletion();
    __shared__ float sA[2 * D], sB[D], sU[D], sV[D];
    __shared__ float sc2;
    __shared__ double sst[5];
    int t = threadIdx.x;
    int i = blockIdx.x * 256 + t;
    bool enc = blockIdx.x < nbn;      // block-uniform

    // ---- deg slice (no dependency; atomics fly while encode proceeds) ----
    if (i < nT8) {
        const int4* d4 = (const int4*)dst;
        int4 a = d4[2 * i];
        int4 b = d4[2 * i + 1];
        atomicAdd(&d_deg[a.x], 1); atomicAdd(&d_deg[a.y], 1);
        atomicAdd(&d_deg[a.z], 1); atomicAdd(&d_deg[a.w], 1);
        atomicAdd(&d_deg[b.x], 1); atomicAdd(&d_deg[b.y], 1);
        atomicAdd(&d_deg[b.z], 1); atomicAdd(&d_deg[b.w], 1);
    }
    if (i == 0)
        for (int k = 0; k < Etail; k++) atomicAdd(&d_deg[dst[nT8 * 8 + k]], 1);

    // ---- encode prologue (inputs only) ----
    float w1a = 0.f, w1b = 0.f, vb1 = 0.f, vgam = 0.f, vbet = 0.f;
    float alpha = 0.f;
    int node = blockIdx.x * 256 + t;
    float2 xv = make_float2(0.f, 0.f);
    if (enc) {
        if (t < D) {
            w1a = w1[2 * t]; w1b = w1[2 * t + 1];
            vb1 = b1[t]; vgam = gam[t]; vbet = bet[t];
            float v = 0.f;
#pragma unroll
            for (int r = 0; r < D; r++) v = fmaf(wb[r], gw[r * D + t], v);
            sV[t] = v;
        }
        alpha = pa[0];
        if (node < n) xv = ((const float2*)x)[node];
        __syncthreads();
        if (t < D) {
            float u = 0.f;
#pragma unroll
            for (int r = 0; r < D; r++) u = fmaf(sV[r], w2[r * D + t], u);
            sU[t] = u;
            float cc = sV[t] * b2[t];
            float Cc = wb[t] * gb[t];
#pragma unroll
            for (int o = 16; o; o >>= 1) {
                cc += __shfl_xor_sync(0xffffffffu, cc, o);
                Cc += __shfl_xor_sync(0xffffffffu, Cc, o);
            }
            if (t == 0) {
                sc2 = cc;
                if (blockIdx.x == 0) d_C = Cc + bb[0];  // same value every replay
            }
        }
    }

    cudaGridDependencySynchronize();  // all blocks: wait for stats_k

    if (enc) {
        if (t < 160) {
            int c = t >> 5, k = t & 31;
            double a = 0.0;
            for (int b = k; b < nbn; b += 32) a += d_part[b][c];
#pragma unroll
            for (int o = 16; o; o >>= 1) a += __shfl_xor_sync(0xffffffffu, a, o);
            if (k == 0) sst[c] = a;
        }
        __syncthreads();
        if (t < D) {
            double invN = 1.0 / (double)n;
            double m0 = sst[0] * invN, m1 = sst[1] * invN;
            double v00 = sst[2] * invN - m0 * m0;
            double v11 = sst[3] * invN - m1 * m1;
            double v01 = sst[4] * invN - m0 * m1;
            float mean = (float)((double)w1a * m0 + (double)w1b * m1) + vb1;
            float var  = (float)((double)w1a * w1a * v00 + 2.0 * (double)w1a * w1b * v01 +
                                 (double)w1b * w1b * v11);
            float scale = vgam * rsqrtf(var + 1e-5f);
            sA[2 * t]     = w1a * scale;
            sA[2 * t + 1] = w1b * scale;
            sB[t] = vb1 * scale + vbet - mean * scale;
        }
        __syncthreads();
        if (node < n) {
            float acc = sc2;
#pragma unroll
            for (int k = 0; k < D; k++) {
                float h = fmaf(sA[2 * k], xv.x, fmaf(sA[2 * k + 1], xv.y, sB[k]));
                float p = h >= 0.f ? h : alpha * h;
                acc = fmaf(sU[k], p, acc);
            }
            d_y[node] = acc;          // unnormalized: deg folded in later
        }
    }
}

// 3) qmul_k: trigger@start (scatter launches + preloads edge indices), then
//    sync on degY_k (deg atomics + y complete), then dinv/q/sacc/deg-rezero.
__global__ void __launch_bounds__(256) qmul_k(int n) {
    cudaTriggerProgrammaticLaunchCompletion();
    cudaGridDependencySynchronize();
    int i = blockIdx.x * 256 + threadIdx.x;
    if (i < n) {
        int dg = __ldcg(&d_deg[i]);   // RED-produced (L2)
        d_deg[i] = 0;                 // re-zero for next graph replay
        float dv = rsqrtf((float)dg + 1.0f);
        float qv = dv * d_y[i];
        d_q[i] = qv;
        d_sacc[i] = qv;               // self-loop prefolded
        d_dinv[i] = dv;
    }
}

// 4) scatter_k: trigger@start; prologue loads edge indices (inputs only);
//    gathers + REDs after sync on qmul_k.
__global__ void __launch_bounds__(256) scatter_k(const int* __restrict__ ei, int E,
                                                 int nT8, int Etail) {
    cudaTriggerProgrammaticLaunchCompletion();
    int i = blockIdx.x * 256 + threadIdx.x;
    int4 s0, s1, t0, t1;
    bool act = i < nT8;
    if (act) {
        const int4* s4 = (const int4*)ei;
        const int4* d4 = (const int4*)(ei + E);
        s0 = s4[2 * i];
        s1 = s4[2 * i + 1];
        t0 = d4[2 * i];
        t1 = d4[2 * i + 1];
    }

    cudaGridDependencySynchronize();  // wait for qmul_k's q/sacc

    if (act) {
        float q0 = __ldg(&d_q[s0.x]);
        float q1 = __ldg(&d_q[s0.y]);
        float q2 = __ldg(&d_q[s0.z]);
        float q3 = __ldg(&d_q[s0.w]);
        float q4 = __ldg(&d_q[s1.x]);
        float q5 = __ldg(&d_q[s1.y]);
        float q6 = __ldg(&d_q[s1.z]);
        float q7 = __ldg(&d_q[s1.w]);
        atomicAdd(&d_sacc[t0.x], q0);
        atomicAdd(&d_sacc[t0.y], q1);
        atomicAdd(&d_sacc[t0.z], q2);
        atomicAdd(&d_sacc[t0.w], q3);
        atomicAdd(&d_sacc[t1.x], q4);
        atomicAdd(&d_sacc[t1.y], q5);
        atomicAdd(&d_sacc[t1.z], q6);
        atomicAdd(&d_sacc[t1.w], q7);
    }
    if (i == 0)
        for (int k = 0; k < Etail; k++) {
            int e = nT8 * 8 + k;
            atomicAdd(&d_sacc[ei[E + e]], __ldg(&d_q[ei[e]]));
        }
}

// 5) score_k: NO early trigger (serializes the replay boundary).
__global__ void __launch_bounds__(128) score_k(float* __restrict__ out, int n4, int n) {
    int i = blockIdx.x * 128 + threadIdx.x;

    cudaGridDependencySynchronize();  // wait for scatter_k's REDs

    float C = d_C;
    if (i < n4) {
        float4 dv = ((const float4*)d_dinv)[i];
        float s0 = __ldcg(&d_sacc[4 * i]);
        float s1 = __ldcg(&d_sacc[4 * i + 1]);
        float s2 = __ldcg(&d_sacc[4 * i + 2]);
        float s3 = __ldcg(&d_sacc[4 * i + 3]);
        float4 o;
        o.x = fmaf(dv.x, s0, C);
        o.y = fmaf(dv.y, s1, C);
        o.z = fmaf(dv.z, s2, C);
        o.w = fmaf(dv.w, s3, C);
        ((float4*)out)[i] = o;
    }
    if (i == 0)
        for (int k = n4 * 4; k < n; k++)
            out[k] = fmaf(d_dinv[k], __ldcg(&d_sacc[k]), C);
}

// ---------------------------------------------------------------------------
static void launch_pdl(void* fn, dim3 grid, dim3 block, void** args) {
    cudaLaunchConfig_t cfg = {};
    cfg.gridDim = grid;
    cfg.blockDim = block;
    cfg.dynamicSmemBytes = 0;
    cfg.stream = 0;
    cudaLaunchAttribute attr[1];
    attr[0].id = cudaLaunchAttributeProgrammaticStreamSerialization;
    attr[0].val.programmaticStreamSerializationAllowed = 1;
    cfg.attrs = attr;
    cfg.numAttrs = 1;
    cudaLaunchKernelExC(&cfg, fn, args);
}

extern "C" void kernel_launch(void* const* d_in, const int* in_sizes, int n_in,
                              void* d_out, int out_size) {
    const float* x   = (const float*)d_in[0];
    const int*   ei  = (const int*)d_in[1];      // int32 (JAX x64 disabled)
    const float* w1  = (const float*)d_in[2];
    const float* b1  = (const float*)d_in[3];
    const float* gam = (const float*)d_in[4];
    const float* bet = (const float*)d_in[5];
    const float* pa  = (const float*)d_in[6];
    const float* w2  = (const float*)d_in[7];
    const float* b2  = (const float*)d_in[8];
    const float* gw  = (const float*)d_in[9];
    const float* gb  = (const float*)d_in[10];
    const float* wb  = (const float*)d_in[11];
    const float* bb  = (const float*)d_in[12];
    int n = in_sizes[0] / 2;
    int E = in_sizes[1] / 2;
    int nT8 = E >> 3;                 // 8 edges per thread
    int Etail = E & 7;
    int nbn = (n + 255) / 256;
    int ebn = (nT8 + 255) / 256;
    if (ebn < nbn) ebn = nbn;         // degY grid must cover encode blocks
    int n4 = n >> 2;
    int sbn = (n4 + 127) / 128;
    float* out = (float*)d_out;
    const int* dst = ei + E;

    {
        void* a[] = { (void*)&x, &n };
        launch_pdl((void*)stats_k, dim3(nbn), dim3(256), a);
    }
    {
        void* a[] = { (void*)&dst, &nT8, &Etail, (void*)&x,
                      (void*)&w1, (void*)&b1, (void*)&gam, (void*)&bet,
                      (void*)&pa, (void*)&w2, (void*)&b2, (void*)&gw, (void*)&gb,
                      (void*)&wb, (void*)&bb, &n, &nbn };
        launch_pdl((void*)degY_k, dim3(ebn), dim3(256), a);
    }
    {
        void* a[] = { &n };
        launch_pdl((void*)qmul_k, dim3(nbn), dim3(256), a);
    }
    {
        void* a[] = { (void*)&ei, &E, &nT8, &Etail };
        launch_pdl((void*)scatter_k, dim3(ebn), dim3(256), a);
    }
    {
        void* a[] = { (void*)&out, &n4, &n };
        launch_pdl((void*)score_k, dim3(sbn), dim3(128), a);
    }
}